// round 14
// baseline (speedup 1.0000x reference)
#include <cuda_runtime.h>

// MorphologicalDegradation, i=30 fixed: k=7 circular SE, dilation, weight=0.24.
//   out = clip(0.76*x + 0.24*(1 - prod_taps(1 - x_shift)), 0, 1)
// Row decomposition (half-widths by dy): {0,2,2,3,2,2,0}:
//   out(s) = f( t(s-3) * h2(s-2) * h2(s-1) * h3(s) * h2(s+1) * h2(s+2) * t(s+3) )
// With G'(r) = h2(r-1)*h2(r):  out(s) = t(s-3) * G'(s-1) * h3(s) * G'(s+2) * t(s+3)
//
// R14 (base = R13, ncu 9.73us): single persistent wave. R13 ran 2048 blocks
// over 1036 resident slots (7/SM) = 1.98 waves, paying the wave transition +
// ragged tail. Now: 1024 blocks (<= 1036 -> ONE fully-resident wave); each
// warp sequentially processes its unit and unit+4096. Perfect balance, and
// unit 2's prologue loads overlap unit 1's pipeline drain inside the warp.
// Keep: ring-4 accumulators + compile-time liveness, depth-4 M prefetch,
// shuffle halos (each pixel loaded once), __stcs stores, pairwise products, G'.

static constexpr int Hh     = 512;
static constexpr int Ww     = 512;
static constexpr int ROUT   = 4;             // output rows per warp-unit
static constexpr int CHUNKS = 128;           // 512/4
static constexpr int ITERS  = ROUT + 6;      // 10 input rows streamed
static constexpr int PDEPTH = 4;             // M-prefetch depth

__device__ __forceinline__ float4 zero4() { return make_float4(0.f, 0.f, 0.f, 0.f); }

__device__ __forceinline__ void run_unit(const float* __restrict__ x,
                                         float* __restrict__ out,
                                         int unit, int ln)
{
    const int wp    = unit & 3;             // column quadrant (128 cols each)
    const int uq    = unit >> 2;            // 0..2047
    const int chunk = uq & (CHUNKS - 1);    // row chunk
    const int img   = uq >> 7;              // 16 images

    const int c0 = wp * 128 + ln * 4;       // first of 4 owned columns
    const int y0 = chunk * ROUT;

    const float* base  = x   + img * (Hh * Ww);
    float*       obase = out + img * (Hh * Ww);

    const float WGT  = 0.24f;
    const float IWGT = 1.0f - 0.24f;

    const bool laneL = (ln == 0)  && (c0 >= 4);          // left warp-boundary load
    const bool laneR = (ln == 31) && (c0 + 4 <= Ww - 4); // right warp-boundary load

    float4 acc[4];   // ring of pending outputs, slot = s & 3

    auto loadM = [&](int ii) -> float4 {
        const int r = y0 - 3 + ii;
        return ((unsigned)r < (unsigned)Hh)
            ? __ldg((const float4*)(base + r * Ww + c0)) : zero4();
    };

    // center-row pipeline, depth 4
    float4 Mp[PDEPTH];
    Mp[0] = loadM(0);
    Mp[1] = loadM(1);
    Mp[2] = loadM(2);
    Mp[3] = loadM(3);

    // previous row's h2 (for G' = h2_prev * h2)
    float hp0 = 1.f, hp1 = 1.f, hp2 = 1.f, hp3 = 1.f;

#pragma unroll
    for (int ii = 0; ii < ITERS; ++ii) {
        const int r = y0 - 3 + ii;

        // compile-time liveness windows (ii is an unroll constant)
        const bool liveInit = (ii <= 3);                  // s = r+3
        const bool liveGp1  = (ii >= 2) && (ii <= 5);     // G' for s = r+1
        const bool liveH3   = (ii >= 3) && (ii <= 6);     // h3 for s = r
        const bool liveGm2  = (ii >= 5) && (ii <= 8);     // G' for s = r-2
        const bool liveEmit = (ii >= 6);                  // s = r-3
        const bool needH2   = (ii >= 1) && (ii <= 8);     // h2(r) used now or as hp next
        const bool needG    = liveGp1 || liveGm2;

        const float4 M0 = Mp[0];

        // prefetch center row at depth PDEPTH
        float4 Mnew = (ii + PDEPTH < ITERS) ? loadM(ii + PDEPTH) : zero4();

        // warp-boundary halos: 1-lane predicated loads (current row, only if h2 needed)
        float4 Lh = zero4(), Rh = zero4();
        if (needH2 && laneL && (unsigned)r < (unsigned)Hh)
            Lh = __ldg((const float4*)(base + r * Ww + c0 - 4));
        if (needH2 && laneR && (unsigned)r < (unsigned)Hh)
            Rh = __ldg((const float4*)(base + r * Ww + c0 + 4));

        // reload raw x for the emit row early (L1 hit; loaded 3 iters ago).
        // y = y0+ii-6 in [y0, y0+3] subset [0,511] -> no bounds check needed.
        const int y = y0 + ii - 6;
        float4 xv;
        if (liveEmit) xv = __ldg((const float4*)(base + y * Ww + c0));

        // own t-values (cols c0..c0+3)
        const float tm0 = 1.f - M0.x, tm1 = 1.f - M0.y, tm2 = 1.f - M0.z, tm3 = 1.f - M0.w;

        float h2[4], h3[4];
        if (needH2) {
            // halo t-values from neighbor lanes
            float t1 = __shfl_up_sync(0xffffffffu, tm1, 1);   // t(c0-3)
            float t2 = __shfl_up_sync(0xffffffffu, tm2, 1);   // t(c0-2)
            float t3 = __shfl_up_sync(0xffffffffu, tm3, 1);   // t(c0-1)
            float t8 = __shfl_down_sync(0xffffffffu, tm0, 1); // t(c0+4)
            float t9 = __shfl_down_sync(0xffffffffu, tm1, 1); // t(c0+5)
            float t10= __shfl_down_sync(0xffffffffu, tm2, 1); // t(c0+6)
            if (ln == 0)  { t1 = 1.f - Lh.y; t2 = 1.f - Lh.z; t3 = 1.f - Lh.w; }
            if (ln == 31) { t8 = 1.f - Rh.x; t9 = 1.f - Rh.y; t10 = 1.f - Rh.z; }
            // (image-edge lanes: Lh/Rh stay zero -> t = 1, matching zero-pad)

            const float t4 = tm0, t5 = tm1, t6 = tm2, t7 = tm3;

            // pairwise-shared horizontal products
            const float p23 = t2 * t3, p45 = t4 * t5, p67 = t6 * t7, p89 = t8 * t9;
            h2[0] = p23 * p45 * t6;       // t2 t3 t4 t5 t6
            h2[1] = t3  * p45 * p67;      // t3 t4 t5 t6 t7
            h2[2] = p45 * p67 * t8;       // t4 t5 t6 t7 t8
            h2[3] = t5  * p67 * p89;      // t5 t6 t7 t8 t9
            if (liveH3) {
                h3[0] = h2[0] * t1 * t7;
                h3[1] = h2[1] * t2 * t8;
                h3[2] = h2[2] * t3 * t9;
                h3[3] = h2[3] * t4 * t10;
            }
        }

        // paired vertical factor: G'(r) = h2(r-1) * h2(r)
        float g0, g1, g2, g3;
        if (needG) {
            g0 = hp0 * h2[0]; g1 = hp1 * h2[1]; g2 = hp2 * h2[2]; g3 = hp3 * h2[3];
        }
        if (needH2) { hp0 = h2[0]; hp1 = h2[1]; hp2 = h2[2]; hp3 = h2[3]; }

        // ring stages, slot = s & 3 (static after unroll)
        if (liveInit)                                 // s = r+3 = y0+ii
            acc[(y0 + ii) & 3] = make_float4(tm0, tm1, tm2, tm3);
        if (liveGp1) { float4& a = acc[(y0 + ii - 2) & 3];   // s = r+1
            a.x *= g0; a.y *= g1; a.z *= g2; a.w *= g3; }
        if (liveH3)  { float4& a = acc[(y0 + ii - 3) & 3];   // s = r
            a.x *= h3[0]; a.y *= h3[1]; a.z *= h3[2]; a.w *= h3[3]; }
        if (liveGm2) { float4& a = acc[(y0 + ii - 5) & 3];   // s = r-2
            a.x *= g0; a.y *= g1; a.z *= g2; a.w *= g3; }

        if (liveEmit) {                               // s = r-3 = y
            float4 a = acc[y & 3];
            a.x *= tm0; a.y *= tm1; a.z *= tm2; a.w *= tm3;

            float4 o;
            float m;
            m   = 1.f - a.x;   // a in [0,1] -> m in [0,1], no extra clip needed
            o.x = fminf(fmaxf(IWGT * xv.x + WGT * m, 0.f), 1.f);
            m   = 1.f - a.y;
            o.y = fminf(fmaxf(IWGT * xv.y + WGT * m, 0.f), 1.f);
            m   = 1.f - a.z;
            o.z = fminf(fmaxf(IWGT * xv.z + WGT * m, 0.f), 1.f);
            m   = 1.f - a.w;
            o.w = fminf(fmaxf(IWGT * xv.w + WGT * m, 0.f), 1.f);

            __stcs((float4*)(obase + y * Ww + c0), o);   // streaming store
        }

        // advance M pipeline
        Mp[0] = Mp[1]; Mp[1] = Mp[2]; Mp[2] = Mp[3]; Mp[3] = Mnew;
    }
}

__global__ void __launch_bounds__(128, 7)
morph_kernel(const float* __restrict__ x, float* __restrict__ out)
{
    const int gt = blockIdx.x * 128 + threadIdx.x;
    const int gw = gt >> 5;            // resident warp id, 0..4095
    const int ln = gt & 31;

    // single persistent wave: each warp handles 2 of the 8192 work units
    run_unit(x, out, gw,        ln);
    run_unit(x, out, gw + 4096, ln);
}

extern "C" void kernel_launch(void* const* d_in, const int* in_sizes, int n_in,
                              void* d_out, int out_size)
{
    (void)in_sizes; (void)n_in; (void)out_size;
    const float* x = (const float*)d_in[0];   // (16,1,512,512) fp32; d_in[1] = i (fixed 30)
    float* o = (float*)d_out;
    // 1024 blocks of 128 threads <= 1036 resident slots (7 blocks/SM x 148)
    // -> ONE fully-resident wave; each warp runs 2 work units sequentially.
    morph_kernel<<<1024, 128>>>(x, o);
}